// round 8
// baseline (speedup 1.0000x reference)
#include <cuda_runtime.h>
#include <cstdint>

#define NITEMS 4096
#define TPB    512
#define NWARP  16
#define CAP    600.0f
#define MU     1e-3f
#define MAXIT  16
#define LAM0   0.82f      // ensemble warm start; bracketed Newton guards any row
#define PHITOL 2.5e-3f    // phi noise floor ~1e-3; lambda err ~3.5e-6, refine cleans up

typedef unsigned long long u64p;   // packed f32x2

__device__ __forceinline__ float frcp(float v) {
    float r;
    asm("rcp.approx.ftz.f32 %0, %1;" : "=f"(r) : "f"(v));
    return r;
}
__device__ __forceinline__ float frsq(float v) {
    float r;
    asm("rsqrt.approx.ftz.f32 %0, %1;" : "=f"(r) : "f"(v));
    return r;
}
__device__ __forceinline__ u64p pack2(float lo, float hi) {
    u64p r;
    asm("mov.b64 %0, {%1, %2};" : "=l"(r) : "f"(lo), "f"(hi));
    return r;
}
__device__ __forceinline__ void unpack2(u64p v, float& lo, float& hi) {
    asm("mov.b64 {%0, %1}, %2;" : "=f"(lo), "=f"(hi) : "l"(v));
}
__device__ __forceinline__ u64p mul2(u64p a, u64p b) {
    u64p r;
    asm("mul.rn.f32x2 %0, %1, %2;" : "=l"(r) : "l"(a), "l"(b));
    return r;
}
__device__ __forceinline__ u64p fma2(u64p a, u64p b, u64p c) {
    u64p r;
    asm("fma.rn.f32x2 %0, %1, %2, %3;" : "=l"(r) : "l"(a), "l"(b), "l"(c));
    return r;
}

__device__ __forceinline__ float wsum32(float v) {
#pragma unroll
    for (int o = 16; o > 0; o >>= 1) v += __shfl_xor_sync(0xffffffffu, v, o);
    return v;
}
__device__ __forceinline__ float bsum16(float v) {
#pragma unroll
    for (int o = 8; o > 0; o >>= 1) v += __shfl_xor_sync(0xffffffffu, v, o);
    return v;
}

// interior root of g x^2 - (g+2mu) x + mu = 0, cancellation-free:
//   t(a) = 2mu / (a + 2mu + sqrt(a^2+4mu^2)),  a = |g|;  x = g>=0 ? t : 1-t
// -dx/dg = t * rden * (1 + a/D)   (same for both signs)
__device__ __forceinline__ void xofg(float g, float& x, float& ndtda) {
    const float a   = fabsf(g);
    const float u   = fmaf(a, a, 4.0f * MU * MU);
    const float rD  = frsq(u);
    const float D   = u * rD;
    const float den = a + 2.0f * MU + D;
    const float rden = frcp(den);
    const float t   = (2.0f * MU) * rden;
    x = (g >= 0.0f) ? t : 1.0f - t;
    ndtda = (t * rden) * fmaf(a, rD, 1.0f);   // = -dx/dg  (positive)
}

// Pass A of the refine (identical math to the reference KKT refine), mu-scaled.
__device__ __forceinline__ void passA(
    const float4* __restrict__ sc, const float4* __restrict__ sw, int tid,
    const u64p* xP, u64p* qS, u64p* wiS, u64p* fiS,
    float lam, u64p one2, u64p none2, u64p n22,
    float& o1, float& o2, float& o3)
{
    const u64p lam2 = pack2(lam, lam);
    const u64p tmu2 = pack2(2.0f * MU, 2.0f * MU);
    const u64p nmu2 = pack2(-MU, -MU);
    u64p s1 = 0ull, s2 = 0ull, s3 = 0ull;
#pragma unroll
    for (int h = 0; h < 2; h++) {
        const float4 cf = sc[h * TPB + tid];
        const float4 wf = sw[h * TPB + tid];
#pragma unroll
        for (int j = 0; j < 2; j++) {
            const int idx = h * 2 + j;
            const u64p cv = j ? pack2(cf.z, cf.w) : pack2(cf.x, cf.y);
            const u64p wv = j ? pack2(wf.z, wf.w) : pack2(wf.x, wf.y);
            const u64p xv = xP[idx];
            const u64p omx = fma2(xv, none2, one2);     // 1-x
            const u64p p   = mul2(xv, omx);             // x(1-x)
            const u64p s   = fma2(p, n22, one2);        // 1-2p
            const u64p p2  = mul2(p, p);
            const u64p arg = mul2(p2, s);
            float a0, a1; unpack2(arg, a0, a1);
            const u64p r   = pack2(frcp(a0), frcp(a1)); // 1/(p^2 s)
            const u64p q   = mul2(r, mul2(p, s));       // 1/p
            const u64p iH  = mul2(r, mul2(p2, p2));     // mu/H
            const u64p t   = fma2(tmu2, xv, nmu2);      // mu(2x-1)
            const u64p f1  = fma2(t, q, fma2(lam2, wv, cv));
            const u64p wiH = mul2(wv, iH);
            qS[idx]  = q;
            wiS[idx] = wiH;
            fiS[idx] = mul2(f1, iH);
            s1 = fma2(xv,  wv, s1);    // sum x w
            s2 = fma2(wiH, f1, s2);    // mu * sum (w/H) F1
            s3 = fma2(wiH, wv, s3);    // mu * sum w^2/H
        }
    }
    float lo, hi;
    unpack2(s1, lo, hi); o1 = lo + hi;
    unpack2(s2, lo, hi); o2 = lo + hi;
    unpack2(s3, lo, hi); o3 = lo + hi;
}

__global__ void __launch_bounds__(TPB, 2)
ipm_kernel(const float* __restrict__ costs,
           const float* __restrict__ wglob,
           float* __restrict__ out)
{
    __shared__ float4 sc[2 * TPB];          // -costs row (16KB)
    __shared__ float4 sw[2 * TPB];          // weights    (16KB)
    __shared__ float sR[2][2][NWARP];       // [parity][s1|s2][warp]
    __shared__ float sA[NWARP], sB[NWARP], sC[NWARP];

    const int tid = threadIdx.x, lane = tid & 31, wid = tid >> 5;
    const float* crow = costs + (size_t)blockIdx.x * NITEMS;

    {
        const float4* cg = (const float4*)crow;
        const float4* wg = (const float4*)wglob;
        const float4 c0 = cg[tid], c1 = cg[TPB + tid];
        sc[tid]       = make_float4(-c0.x, -c0.y, -c0.z, -c0.w);
        sc[TPB + tid] = make_float4(-c1.x, -c1.y, -c1.z, -c1.w);
        sw[tid]       = wg[tid];
        sw[TPB + tid] = wg[TPB + tid];
    }
    __syncthreads();

    // ---- 1-D safeguarded Newton on lambda:  phi(lam) = sum w*x(lam) - CAP --
    float lam = LAM0, lo = -30.0f, hi = 30.0f;

#pragma unroll 1
    for (int it = 0; it < MAXIT; ++it) {
        float s1 = 0.0f, s2 = 0.0f;     // s1 = sum w x, s2 = -phi'
#pragma unroll
        for (int h = 0; h < 2; h++) {
            const float4 cf = sc[h * TPB + tid];
            const float4 wf = sw[h * TPB + tid];
            float x, nd;
            xofg(fmaf(lam, wf.x, cf.x), x, nd);
            s1 = fmaf(wf.x, x, s1); s2 = fmaf(wf.x * wf.x, nd, s2);
            xofg(fmaf(lam, wf.y, cf.y), x, nd);
            s1 = fmaf(wf.y, x, s1); s2 = fmaf(wf.y * wf.y, nd, s2);
            xofg(fmaf(lam, wf.z, cf.z), x, nd);
            s1 = fmaf(wf.z, x, s1); s2 = fmaf(wf.z * wf.z, nd, s2);
            xofg(fmaf(lam, wf.w, cf.w), x, nd);
            s1 = fmaf(wf.w, x, s1); s2 = fmaf(wf.w * wf.w, nd, s2);
        }
        s1 = wsum32(s1); s2 = wsum32(s2);
        const int par = it & 1;
        if (lane == 0) { sR[par][0][wid] = s1; sR[par][1][wid] = s2; }
        __syncthreads();
        s1 = bsum16(sR[par][0][lane & 15]);     // identical in all threads
        s2 = bsum16(sR[par][1][lane & 15]);

        const float phi = s1 - CAP;
        if (fabsf(phi) < PHITOL) break;            // exit pre-move: lam is final
        if (phi > 0.0f) lo = lam; else hi = lam;   // phi monotone decreasing
        float ln = lam + phi * frcp(s2);           // Newton (phi' = -s2)
        if (!(ln > lo && ln < hi)) ln = 0.5f * (lo + hi);
        lam = ln;
    }

    // ---- build x(lam) elementwise (exact F1 = 0 by construction) -----------
    u64p xP[4], qS[4], wiS[4], fiS[4];
#pragma unroll
    for (int h = 0; h < 2; h++) {
        const float4 cf = sc[h * TPB + tid];
        const float4 wf = sw[h * TPB + tid];
        float x0, x1, x2, x3, nd;
        xofg(fmaf(lam, wf.x, cf.x), x0, nd);
        xofg(fmaf(lam, wf.y, cf.y), x1, nd);
        xofg(fmaf(lam, wf.z, cf.z), x2, nd);
        xofg(fmaf(lam, wf.w, cf.w), x3, nd);
        xP[h * 2]     = pack2(x0, x1);
        xP[h * 2 + 1] = pack2(x2, x3);
    }

    const u64p one2  = pack2(1.0f, 1.0f);
    const u64p none2 = pack2(-1.0f, -1.0f);
    const u64p n22   = pack2(-2.0f, -2.0f);

    // ---- KKT refine at mu = MU (same as reference): out = x + dx -----------
    {
        float s1, s2, s3;
        passA(sc, sw, tid, xP, qS, wiS, fiS, lam, one2, none2, n22, s1, s2, s3);
        s1 = wsum32(s1); s2 = wsum32(s2); s3 = wsum32(s3);
        if (lane == 0) { sA[wid] = s1; sB[wid] = s2; sC[wid] = s3; }
        __syncthreads();
        const float A  = bsum16(sA[lane & 15]);
        const float Bv = bsum16(sB[lane & 15]);
        const float Cv = bsum16(sC[lane & 15]);
        const float dlam = (MU * (A - CAP) - Bv) * frcp(Cv);   // scalar Schur

        const u64p dl2 = pack2(dlam, dlam);
        const float inv_mu = 1.0f / MU;
        const u64p ni2 = pack2(-inv_mu, -inv_mu);

        float4* orow = (float4*)(out + (size_t)blockIdx.x * NITEMS);
#pragma unroll
        for (int h = 0; h < 2; h++) {
            float4 o;
            {
                const int idx = h * 2;
                const u64p mm = fma2(dl2, wiS[idx], fiS[idx]);   // (F1+dlam w)*mu/H
                const u64p ov = fma2(ni2, mm, xP[idx]);          // x + dx
                unpack2(ov, o.x, o.y);
            }
            {
                const int idx = h * 2 + 1;
                const u64p mm = fma2(dl2, wiS[idx], fiS[idx]);
                const u64p ov = fma2(ni2, mm, xP[idx]);
                unpack2(ov, o.z, o.w);
            }
            orow[h * TPB + tid] = o;
        }
    }
}

extern "C" void kernel_launch(void* const* d_in, const int* in_sizes, int n_in,
                              void* d_out, int out_size)
{
    const float* costs = (const float*)d_in[0];
    const float* wv    = (const float*)d_in[1];
    int costs_elems = in_sizes[0];
    if (n_in >= 2 && in_sizes[0] == NITEMS && in_sizes[1] > NITEMS) {
        costs = (const float*)d_in[1];
        wv    = (const float*)d_in[0];
        costs_elems = in_sizes[1];
    }
    const int B = costs_elems / NITEMS;
    ipm_kernel<<<B, TPB>>>(costs, wv, (float*)d_out);
}

// round 9
// speedup vs baseline: 1.7620x; 1.7620x over previous
#include <cuda_runtime.h>
#include <cstdint>

#define NITEMS 4096
#define TPB    512
#define NWARP  16
#define CAP    600.0f
#define MU     1e-3f
#define MAXIT  16
#define LAM0   0.82f      // ensemble warm start (integral estimate lam* ~ 0.83)
#define PHITOL 5e-3f      // phi gate; lam err ~7e-6, KKT refine cleans to ~1e-6

typedef unsigned long long u64p;   // packed f32x2

__device__ __forceinline__ float frcp(float v) {
    float r;
    asm("rcp.approx.ftz.f32 %0, %1;" : "=f"(r) : "f"(v));
    return r;
}
__device__ __forceinline__ float frsq(float v) {
    float r;
    asm("rsqrt.approx.ftz.f32 %0, %1;" : "=f"(r) : "f"(v));
    return r;
}
__device__ __forceinline__ u64p pack2(float lo, float hi) {
    u64p r;
    asm("mov.b64 %0, {%1, %2};" : "=l"(r) : "f"(lo), "f"(hi));
    return r;
}
__device__ __forceinline__ void unpack2(u64p v, float& lo, float& hi) {
    asm("mov.b64 {%0, %1}, %2;" : "=f"(lo), "=f"(hi) : "l"(v));
}
__device__ __forceinline__ u64p mul2(u64p a, u64p b) {
    u64p r;
    asm("mul.rn.f32x2 %0, %1, %2;" : "=l"(r) : "l"(a), "l"(b));
    return r;
}
__device__ __forceinline__ u64p fma2(u64p a, u64p b, u64p c) {
    u64p r;
    asm("fma.rn.f32x2 %0, %1, %2, %3;" : "=l"(r) : "l"(a), "l"(b), "l"(c));
    return r;
}

__device__ __forceinline__ float wsum32(float v) {
#pragma unroll
    for (int o = 16; o > 0; o >>= 1) v += __shfl_xor_sync(0xffffffffu, v, o);
    return v;
}
__device__ __forceinline__ float bsum16(float v) {
#pragma unroll
    for (int o = 8; o > 0; o >>= 1) v += __shfl_xor_sync(0xffffffffu, v, o);
    return v;
}

// interior root of g x^2 - (g+2mu) x + mu = 0, cancellation-free:
//   t(a) = 2mu / (a + 2mu + sqrt(a^2+4mu^2)),  a = |g|;  x = g>=0 ? t : 1-t
// -dx/dg = t * rden * (1 + a/D)   (same for both signs)
__device__ __forceinline__ void xofg(float g, float& x, float& ndtda) {
    const float a   = fabsf(g);
    const float u   = fmaf(a, a, 4.0f * MU * MU);
    const float rD  = frsq(u);
    const float D   = u * rD;
    const float den = a + 2.0f * MU + D;
    const float rden = frcp(den);
    const float t   = (2.0f * MU) * rden;
    x = (g >= 0.0f) ? t : 1.0f - t;
    ndtda = (t * rden) * fmaf(a, rD, 1.0f);   // = -dx/dg  (positive)
}

// Pass A of the KKT refine (identical math to the reference), mu-scaled.
__device__ __forceinline__ void passA(
    const float4* __restrict__ sc, const float4* __restrict__ sw, int tid,
    const u64p* xP, u64p* wiS, u64p* fiS,
    float lam, u64p one2, u64p none2, u64p n22,
    float& o1, float& o2, float& o3)
{
    const u64p lam2 = pack2(lam, lam);
    const u64p tmu2 = pack2(2.0f * MU, 2.0f * MU);
    const u64p nmu2 = pack2(-MU, -MU);
    u64p s1 = 0ull, s2 = 0ull, s3 = 0ull;
#pragma unroll
    for (int h = 0; h < 2; h++) {
        const float4 cf = sc[h * TPB + tid];
        const float4 wf = sw[h * TPB + tid];
#pragma unroll
        for (int j = 0; j < 2; j++) {
            const int idx = h * 2 + j;
            const u64p cv = j ? pack2(cf.z, cf.w) : pack2(cf.x, cf.y);
            const u64p wv = j ? pack2(wf.z, wf.w) : pack2(wf.x, wf.y);
            const u64p xv = xP[idx];
            const u64p omx = fma2(xv, none2, one2);     // 1-x
            const u64p p   = mul2(xv, omx);             // x(1-x)
            const u64p s   = fma2(p, n22, one2);        // 1-2p
            const u64p p2  = mul2(p, p);
            const u64p arg = mul2(p2, s);
            float a0, a1; unpack2(arg, a0, a1);
            const u64p r   = pack2(frcp(a0), frcp(a1)); // 1/(p^2 s)
            const u64p q   = mul2(r, mul2(p, s));       // 1/p
            const u64p iH  = mul2(r, mul2(p2, p2));     // mu/H
            const u64p t   = fma2(tmu2, xv, nmu2);      // mu(2x-1)
            const u64p f1  = fma2(t, q, fma2(lam2, wv, cv));
            const u64p wiH = mul2(wv, iH);
            wiS[idx] = wiH;
            fiS[idx] = mul2(f1, iH);
            s1 = fma2(xv,  wv, s1);    // sum x w
            s2 = fma2(wiH, f1, s2);    // mu * sum (w/H) F1
            s3 = fma2(wiH, wv, s3);    // mu * sum w^2/H
        }
    }
    float lo, hi;
    unpack2(s1, lo, hi); o1 = lo + hi;
    unpack2(s2, lo, hi); o2 = lo + hi;
    unpack2(s3, lo, hi); o3 = lo + hi;
}

__global__ void __launch_bounds__(TPB, 2)
ipm_kernel(const float* __restrict__ costs,
           const float* __restrict__ wglob,
           float* __restrict__ out)
{
    __shared__ float4 sc[2 * TPB];          // -costs row (16KB)
    __shared__ float4 sw[2 * TPB];          // weights    (16KB)
    __shared__ float sR[2][2][NWARP];       // [parity][s1|s2][warp]
    __shared__ float sA[NWARP], sB[NWARP], sC[NWARP];

    const int tid = threadIdx.x, lane = tid & 31, wid = tid >> 5;
    const float* crow = costs + (size_t)blockIdx.x * NITEMS;

    {
        const float4* cg = (const float4*)crow;
        const float4* wg = (const float4*)wglob;
        const float4 c0 = cg[tid], c1 = cg[TPB + tid];
        sc[tid]       = make_float4(-c0.x, -c0.y, -c0.z, -c0.w);
        sc[TPB + tid] = make_float4(-c1.x, -c1.y, -c1.z, -c1.w);
        sw[tid]       = wg[tid];
        sw[TPB + tid] = wg[TPB + tid];
    }
    __syncthreads();

    // ---- 1-D safeguarded Newton on lambda:  phi(lam) = sum w*x(lam) - CAP --
    // Every pass also stashes x(lam) into xP; the pre-move exit means xP is
    // exactly x(final lam) on break -> no separate rebuild pass needed.
    float lam = LAM0, lo = -30.0f, hi = 30.0f;
    u64p xP[4];
    bool built = false;

#pragma unroll 1
    for (int it = 0; it < MAXIT; ++it) {
        float s1 = 0.0f, s2 = 0.0f;     // s1 = sum w x, s2 = -phi'
#pragma unroll
        for (int h = 0; h < 2; h++) {
            const float4 cf = sc[h * TPB + tid];
            const float4 wf = sw[h * TPB + tid];
            float x0, x1, x2, x3, nd;
            xofg(fmaf(lam, wf.x, cf.x), x0, nd);
            s1 = fmaf(wf.x, x0, s1); s2 = fmaf(wf.x * wf.x, nd, s2);
            xofg(fmaf(lam, wf.y, cf.y), x1, nd);
            s1 = fmaf(wf.y, x1, s1); s2 = fmaf(wf.y * wf.y, nd, s2);
            xofg(fmaf(lam, wf.z, cf.z), x2, nd);
            s1 = fmaf(wf.z, x2, s1); s2 = fmaf(wf.z * wf.z, nd, s2);
            xofg(fmaf(lam, wf.w, cf.w), x3, nd);
            s1 = fmaf(wf.w, x3, s1); s2 = fmaf(wf.w * wf.w, nd, s2);
            xP[h * 2]     = pack2(x0, x1);
            xP[h * 2 + 1] = pack2(x2, x3);
        }
        s1 = wsum32(s1); s2 = wsum32(s2);
        const int par = it & 1;
        if (lane == 0) { sR[par][0][wid] = s1; sR[par][1][wid] = s2; }
        __syncthreads();
        s1 = bsum16(sR[par][0][lane & 15]);     // identical in all threads
        s2 = bsum16(sR[par][1][lane & 15]);

        const float phi = s1 - CAP;
        if (fabsf(phi) < PHITOL) { built = true; break; }   // lam stays -> xP valid
        if (phi > 0.0f) lo = lam; else hi = lam;            // phi monotone dec.
        float ln = lam + phi * frcp(s2);                    // Newton (phi' = -s2)
        if (!(ln > lo && ln < hi)) ln = 0.5f * (lo + hi);
        lam = ln;
    }

    // Fallback (cold path): lam moved after the last stash -> rebuild x(lam).
    if (!built) {
#pragma unroll
        for (int h = 0; h < 2; h++) {
            const float4 cf = sc[h * TPB + tid];
            const float4 wf = sw[h * TPB + tid];
            float x0, x1, x2, x3, nd;
            xofg(fmaf(lam, wf.x, cf.x), x0, nd);
            xofg(fmaf(lam, wf.y, cf.y), x1, nd);
            xofg(fmaf(lam, wf.z, cf.z), x2, nd);
            xofg(fmaf(lam, wf.w, cf.w), x3, nd);
            xP[h * 2]     = pack2(x0, x1);
            xP[h * 2 + 1] = pack2(x2, x3);
        }
    }

    const u64p one2  = pack2(1.0f, 1.0f);
    const u64p none2 = pack2(-1.0f, -1.0f);
    const u64p n22   = pack2(-2.0f, -2.0f);

    // ---- KKT refine at mu = MU (same as reference): out = x + dx -----------
    {
        u64p wiS[4], fiS[4];
        float s1, s2, s3;
        passA(sc, sw, tid, xP, wiS, fiS, lam, one2, none2, n22, s1, s2, s3);
        s1 = wsum32(s1); s2 = wsum32(s2); s3 = wsum32(s3);
        if (lane == 0) { sA[wid] = s1; sB[wid] = s2; sC[wid] = s3; }
        __syncthreads();
        const float A  = bsum16(sA[lane & 15]);
        const float Bv = bsum16(sB[lane & 15]);
        const float Cv = bsum16(sC[lane & 15]);
        const float dlam = (MU * (A - CAP) - Bv) * frcp(Cv);   // scalar Schur

        const u64p dl2 = pack2(dlam, dlam);
        const float inv_mu = 1.0f / MU;
        const u64p ni2 = pack2(-inv_mu, -inv_mu);

        float4* orow = (float4*)(out + (size_t)blockIdx.x * NITEMS);
#pragma unroll
        for (int h = 0; h < 2; h++) {
            float4 o;
            {
                const int idx = h * 2;
                const u64p mm = fma2(dl2, wiS[idx], fiS[idx]);   // (F1+dlam w)*mu/H
                const u64p ov = fma2(ni2, mm, xP[idx]);          // x + dx
                unpack2(ov, o.x, o.y);
            }
            {
                const int idx = h * 2 + 1;
                const u64p mm = fma2(dl2, wiS[idx], fiS[idx]);
                const u64p ov = fma2(ni2, mm, xP[idx]);
                unpack2(ov, o.z, o.w);
            }
            orow[h * TPB + tid] = o;
        }
    }
}

extern "C" void kernel_launch(void* const* d_in, const int* in_sizes, int n_in,
                              void* d_out, int out_size)
{
    const float* costs = (const float*)d_in[0];
    const float* wv    = (const float*)d_in[1];
    int costs_elems = in_sizes[0];
    if (n_in >= 2 && in_sizes[0] == NITEMS && in_sizes[1] > NITEMS) {
        costs = (const float*)d_in[1];
        wv    = (const float*)d_in[0];
        costs_elems = in_sizes[1];
    }
    const int B = costs_elems / NITEMS;
    ipm_kernel<<<B, TPB>>>(costs, wv, (float*)d_out);
}

// round 10
// speedup vs baseline: 2.2058x; 1.2519x over previous
#include <cuda_runtime.h>
#include <cstdint>

#define NITEMS 4096
#define TPB    512
#define NWARP  16
#define CAP    600.0f
#define MU     1e-3f
#define MAXIT  16
#define LAM0   0.82f      // ensemble warm start (integral estimate lam* ~ 0.83)
#define PHITOL 5e-3f      // exit gate; final Taylor correction absorbs residual

typedef unsigned long long u64p;   // packed f32x2

__device__ __forceinline__ float frcp(float v) {
    float r;
    asm("rcp.approx.ftz.f32 %0, %1;" : "=f"(r) : "f"(v));
    return r;
}
__device__ __forceinline__ float frsq(float v) {
    float r;
    asm("rsqrt.approx.ftz.f32 %0, %1;" : "=f"(r) : "f"(v));
    return r;
}
__device__ __forceinline__ u64p pack2(float lo, float hi) {
    u64p r;
    asm("mov.b64 %0, {%1, %2};" : "=l"(r) : "f"(lo), "f"(hi));
    return r;
}
__device__ __forceinline__ void unpack2(u64p v, float& lo, float& hi) {
    asm("mov.b64 {%0, %1}, %2;" : "=f"(lo), "=f"(hi) : "l"(v));
}

__device__ __forceinline__ float wsum32(float v) {
#pragma unroll
    for (int o = 16; o > 0; o >>= 1) v += __shfl_xor_sync(0xffffffffu, v, o);
    return v;
}
// reduce 16 per-warp partials duplicated across the warp (idx = lane&15)
__device__ __forceinline__ float bsum16(float v) {
#pragma unroll
    for (int o = 8; o > 0; o >>= 1) v += __shfl_xor_sync(0xffffffffu, v, o);
    return v;
}

// interior root of g x^2 - (g+2mu) x + mu = 0, cancellation-free:
//   t(a) = 2mu / (a + 2mu + sqrt(a^2+4mu^2)),  a = |g|;  x = g>=0 ? t : 1-t
// nd = -dx/dg = t * rden * (1 + a/D) = 1/H  (same for both signs)
__device__ __forceinline__ void xofg(float g, float& x, float& nd) {
    const float a   = fabsf(g);
    const float u   = fmaf(a, a, 4.0f * MU * MU);
    const float rD  = frsq(u);
    const float den = fmaf(u, rD, a + 2.0f * MU);   // a + 2mu + sqrt(u)
    const float rden = frcp(den);
    const float t   = (2.0f * MU) * rden;
    x  = (g >= 0.0f) ? t : 1.0f - t;
    nd = (t * rden) * fmaf(a, rD, 1.0f);
}

__global__ void __launch_bounds__(TPB, 2)
ipm_kernel(const float* __restrict__ costs,
           const float* __restrict__ wglob,
           float* __restrict__ out)
{
    __shared__ float4 sc[2 * TPB];          // costs row (raw; g = lam*w - cost)
    __shared__ float4 sw[2 * TPB];          // weights
    __shared__ float sR[2][2][NWARP];       // [parity][s1|s2][warp]

    const int tid = threadIdx.x, lane = tid & 31, wid = tid >> 5;
    const float* crow = costs + (size_t)blockIdx.x * NITEMS;

    {
        const float4* cg = (const float4*)crow;
        const float4* wg = (const float4*)wglob;
        sc[tid]       = cg[tid];
        sc[TPB + tid] = cg[TPB + tid];
        sw[tid]       = wg[tid];
        sw[TPB + tid] = wg[TPB + tid];
    }
    __syncthreads();

    // ---- 1-D safeguarded Newton on lambda:  phi(lam) = sum w*x(lam) - CAP --
    // Each pass stashes x and nd = 1/H. On exit, the (unclamped) Newton step
    // dlam = phi/s2 IS the reference's KKT-refine dlam (F1 = 0 by construction),
    // and dx = -dlam*w*nd, so the output needs no extra pass.
    float lam = LAM0, lo = -30.0f, hi = 30.0f;
    u64p xP[4], ndP[4];
    float dlam = 0.0f;

#pragma unroll 1
    for (int it = 0; it < MAXIT; ++it) {
        float s1 = 0.0f, s2 = 0.0f;     // s1 = sum w x, s2 = sum w^2/H = -phi'
#pragma unroll
        for (int h = 0; h < 2; h++) {
            const float4 cf = sc[h * TPB + tid];
            const float4 wf = sw[h * TPB + tid];
            float x0, x1, x2, x3, n0, n1, n2, n3;
            xofg(fmaf(lam, wf.x, -cf.x), x0, n0);
            s1 = fmaf(wf.x, x0, s1); s2 = fmaf(wf.x * wf.x, n0, s2);
            xofg(fmaf(lam, wf.y, -cf.y), x1, n1);
            s1 = fmaf(wf.y, x1, s1); s2 = fmaf(wf.y * wf.y, n1, s2);
            xofg(fmaf(lam, wf.z, -cf.z), x2, n2);
            s1 = fmaf(wf.z, x2, s1); s2 = fmaf(wf.z * wf.z, n2, s2);
            xofg(fmaf(lam, wf.w, -cf.w), x3, n3);
            s1 = fmaf(wf.w, x3, s1); s2 = fmaf(wf.w * wf.w, n3, s2);
            xP[h * 2]      = pack2(x0, x1);
            xP[h * 2 + 1]  = pack2(x2, x3);
            ndP[h * 2]     = pack2(n0, n1);
            ndP[h * 2 + 1] = pack2(n2, n3);
        }
        s1 = wsum32(s1); s2 = wsum32(s2);
        const int par = it & 1;
        if (lane == 0) { sR[par][0][wid] = s1; sR[par][1][wid] = s2; }
        __syncthreads();
        s1 = bsum16(sR[par][0][lane & 15]);     // identical in all threads
        s2 = bsum16(sR[par][1][lane & 15]);

        const float phi  = s1 - CAP;
        const float step = phi * frcp(s2);      // Newton increment (phi' = -s2)
        if (fabsf(phi) < PHITOL || it == MAXIT - 1) {
            dlam = step;                        // final first-order correction
            break;                              // xP/ndP match current lam
        }
        if (phi > 0.0f) lo = lam; else hi = lam;  // phi monotone decreasing
        float ln = lam + step;
        if (!(ln > lo && ln < hi)) ln = 0.5f * (lo + hi);
        lam = ln;
    }

    // ---- emit: out = x - dlam * w * nd  (== reference KKT refine) ----------
    {
        const float ndl = -dlam;
        float4* orow = (float4*)(out + (size_t)blockIdx.x * NITEMS);
#pragma unroll
        for (int h = 0; h < 2; h++) {
            const float4 wf = sw[h * TPB + tid];
            float x0, x1, x2, x3, n0, n1, n2, n3;
            unpack2(xP[h * 2],      x0, x1);
            unpack2(xP[h * 2 + 1],  x2, x3);
            unpack2(ndP[h * 2],     n0, n1);
            unpack2(ndP[h * 2 + 1], n2, n3);
            float4 o;
            o.x = fmaf(ndl * wf.x, n0, x0);
            o.y = fmaf(ndl * wf.y, n1, x1);
            o.z = fmaf(ndl * wf.z, n2, x2);
            o.w = fmaf(ndl * wf.w, n3, x3);
            orow[h * TPB + tid] = o;
        }
    }
}

extern "C" void kernel_launch(void* const* d_in, const int* in_sizes, int n_in,
                              void* d_out, int out_size)
{
    const float* costs = (const float*)d_in[0];
    const float* wv    = (const float*)d_in[1];
    int costs_elems = in_sizes[0];
    if (n_in >= 2 && in_sizes[0] == NITEMS && in_sizes[1] > NITEMS) {
        costs = (const float*)d_in[1];
        wv    = (const float*)d_in[0];
        costs_elems = in_sizes[1];
    }
    const int B = costs_elems / NITEMS;
    ipm_kernel<<<B, TPB>>>(costs, wv, (float*)d_out);
}

// round 12
// speedup vs baseline: 2.4099x; 1.0925x over previous
#include <cuda_runtime.h>
#include <cstdint>

#define NITEMS 4096
#define TPB    512
#define NWARP  16
#define CAP    600.0f
#define MU     1e-3f
#define MAXIT  16
#define LAM0   0.82f      // ensemble warm start (integral estimate lam* ~ 0.83)
#define PHITOL 5e-3f      // exit gate; first-order emit correction absorbs residual

typedef unsigned long long u64p;   // packed f32x2

__device__ __forceinline__ float frcp(float v) {
    float r;
    asm("rcp.approx.ftz.f32 %0, %1;" : "=f"(r) : "f"(v));
    return r;
}
__device__ __forceinline__ float frsq(float v) {
    float r;
    asm("rsqrt.approx.ftz.f32 %0, %1;" : "=f"(r) : "f"(v));
    return r;
}
__device__ __forceinline__ u64p pack2(float lo, float hi) {
    u64p r;
    asm("mov.b64 %0, {%1, %2};" : "=l"(r) : "f"(lo), "f"(hi));
    return r;
}
__device__ __forceinline__ void unpack2(u64p v, float& lo, float& hi) {
    asm("mov.b64 {%0, %1}, %2;" : "=f"(lo), "=f"(hi) : "l"(v));
}

__device__ __forceinline__ float wsum32(float v) {
#pragma unroll
    for (int o = 16; o > 0; o >>= 1) v += __shfl_xor_sync(0xffffffffu, v, o);
    return v;
}
// reduce 16 per-warp partials duplicated across the warp (idx = lane&15)
__device__ __forceinline__ float bsum16(float v) {
#pragma unroll
    for (int o = 8; o > 0; o >>= 1) v += __shfl_xor_sync(0xffffffffu, v, o);
    return v;
}

// interior root of g x^2 - (g+2mu) x + mu = 0, cancellation-free:
//   t(a) = 2mu / (a + 2mu + sqrt(a^2+4mu^2)),  a = |g|;  x = g>=0 ? t : 1-t
// nd = -dx/dg = t * rden * (1 + a/D) = 1/H  (same value for both signs)
__device__ __forceinline__ void xofg(float g, float& x, float& nd) {
    const float a    = fabsf(g);
    const float u    = fmaf(a, a, 4.0f * MU * MU);
    const float rD   = frsq(u);
    const float den  = fmaf(u, rD, a + 2.0f * MU);   // a + 2mu + sqrt(u)
    const float rden = frcp(den);
    const float t    = (2.0f * MU) * rden;
    x  = (g >= 0.0f) ? t : 1.0f - t;
    nd = (t * rden) * fmaf(a, rD, 1.0f);
}

// one elementwise evaluation quad at lam, accumulating s1/s2 and stashing x, nd
#define EVAL_QUAD(cf, wf, base)                                              \
    do {                                                                     \
        float x0, x1, x2, x3, n0, n1, n2, n3;                                \
        xofg(fmaf(lam, wf.x, -cf.x), x0, n0);                                \
        s1 = fmaf(wf.x, x0, s1); s2 = fmaf(wf.x * wf.x, n0, s2);             \
        xofg(fmaf(lam, wf.y, -cf.y), x1, n1);                                \
        s1 = fmaf(wf.y, x1, s1); s2 = fmaf(wf.y * wf.y, n1, s2);             \
        xofg(fmaf(lam, wf.z, -cf.z), x2, n2);                                \
        s1 = fmaf(wf.z, x2, s1); s2 = fmaf(wf.z * wf.z, n2, s2);             \
        xofg(fmaf(lam, wf.w, -cf.w), x3, n3);                                \
        s1 = fmaf(wf.w, x3, s1); s2 = fmaf(wf.w * wf.w, n3, s2);             \
        xP[base]      = pack2(x0, x1);                                       \
        xP[base + 1]  = pack2(x2, x3);                                       \
        ndP[base]     = pack2(n0, n1);                                       \
        ndP[base + 1] = pack2(n2, n3);                                       \
    } while (0)

__global__ void __launch_bounds__(TPB, 2)
ipm_kernel(const float* __restrict__ costs,
           const float* __restrict__ wglob,
           float* __restrict__ out)
{
    __shared__ float4 sc[2 * TPB];          // costs row (raw; g = lam*w - cost)
    __shared__ float sR[2][2][NWARP];       // [parity][s1|s2][warp]

    const int tid = threadIdx.x, lane = tid & 31, wid = tid >> 5;
    const float* crow = costs + (size_t)blockIdx.x * NITEMS;

    float lam = LAM0, lo = -30.0f, hi = 30.0f;
    u64p xP[4], ndP[4];
    float dlam = 0.0f;
    float4 wf0, wf1;                        // weights resident in registers
    float s1 = 0.0f, s2 = 0.0f;

    // ---- load + fused first evaluation at LAM0 -----------------------------
    {
        const float4* cg = (const float4*)crow;
        const float4* wg = (const float4*)wglob;
        const float4 cf0 = cg[tid], cf1 = cg[TPB + tid];
        wf0 = wg[tid]; wf1 = wg[TPB + tid];
        sc[tid] = cf0; sc[TPB + tid] = cf1;
        EVAL_QUAD(cf0, wf0, 0);
        EVAL_QUAD(cf1, wf1, 2);
        // sc stores are fenced by the __syncthreads in the first reduction
    }

    // ---- 1-D safeguarded (bracketed) Newton on lambda ----------------------
    //   phi(lam) = sum w*x(lam) - CAP,  phi' = -s2
    // On exit, dlam = phi/s2 equals the reference's KKT-refine dlam (F1 = 0 by
    // construction) and dx = -dlam*w*nd -> output emitted without extra pass.
#pragma unroll 1
    for (int it = 0; it < MAXIT; ++it) {
        float r1 = wsum32(s1), r2 = wsum32(s2);
        const int par = it & 1;
        if (lane == 0) { sR[par][0][wid] = r1; sR[par][1][wid] = r2; }
        __syncthreads();
        r1 = bsum16(sR[par][0][lane & 15]);     // identical in all threads
        r2 = bsum16(sR[par][1][lane & 15]);

        const float phi  = r1 - CAP;
        const float step = phi * frcp(r2);      // Newton increment
        if (fabsf(phi) < PHITOL || it == MAXIT - 1) {
            dlam = step;                        // final first-order correction
            break;                              // xP/ndP match current lam
        }
        if (phi > 0.0f) lo = lam; else hi = lam;   // phi monotone decreasing
        float ln = lam + step;
        if (!(ln > lo && ln < hi)) ln = 0.5f * (lo + hi);
        lam = ln;

        // next evaluation: costs from shared, weights from registers
        s1 = 0.0f; s2 = 0.0f;
        {
            const float4 cf0 = sc[tid], cf1 = sc[TPB + tid];
            EVAL_QUAD(cf0, wf0, 0);
            EVAL_QUAD(cf1, wf1, 2);
        }
    }

    // ---- emit: out = x - dlam * w * nd  (== reference KKT refine) ----------
    {
        const float ndl = -dlam;
        float4* orow = (float4*)(out + (size_t)blockIdx.x * NITEMS);
        float x0, x1, x2, x3, n0, n1, n2, n3;
        float4 o;
        unpack2(xP[0], x0, x1);  unpack2(xP[1], x2, x3);
        unpack2(ndP[0], n0, n1); unpack2(ndP[1], n2, n3);
        o.x = fmaf(ndl * wf0.x, n0, x0);
        o.y = fmaf(ndl * wf0.y, n1, x1);
        o.z = fmaf(ndl * wf0.z, n2, x2);
        o.w = fmaf(ndl * wf0.w, n3, x3);
        orow[tid] = o;
        unpack2(xP[2], x0, x1);  unpack2(xP[3], x2, x3);
        unpack2(ndP[2], n0, n1); unpack2(ndP[3], n2, n3);
        o.x = fmaf(ndl * wf1.x, n0, x0);
        o.y = fmaf(ndl * wf1.y, n1, x1);
        o.z = fmaf(ndl * wf1.z, n2, x2);
        o.w = fmaf(ndl * wf1.w, n3, x3);
        orow[TPB + tid] = o;
    }
}

extern "C" void kernel_launch(void* const* d_in, const int* in_sizes, int n_in,
                              void* d_out, int out_size)
{
    const float* costs = (const float*)d_in[0];
    const float* wv    = (const float*)d_in[1];
    int costs_elems = in_sizes[0];
    if (n_in >= 2 && in_sizes[0] == NITEMS && in_sizes[1] > NITEMS) {
        costs = (const float*)d_in[1];
        wv    = (const float*)d_in[0];
        costs_elems = in_sizes[1];
    }
    const int B = costs_elems / NITEMS;
    ipm_kernel<<<B, TPB>>>(costs, wv, (float*)d_out);
}